// round 2
// baseline (speedup 1.0000x reference)
#include <cuda_runtime.h>
#include <cstdint>
#include <cstddef>

#define Dm    512
#define Bm_   16
#define Sm    4096
#define G3    1536
#define NSCAN 128
#define TCH   128                      // timesteps per producer chunk
#define NCH   32                       // Sm / TCH
#define T1PC  (Bm_ * (G3 / 64))        // 384 gi tiles per chunk
#define NT1   (NCH * T1PC)             // 12288
#define T2PC  (Bm_ * (Dm / 64))        // 128 out tiles per chunk
#define NT2   (NCH * T2PC)             // 4096
#define NTOT  (NSCAN + NT1 + NT2)      // 16512
#define SMEMB 63488

// Scratch (device globals: allocation-free per harness rules)
__device__ float    g_gi[(size_t)Bm_ * Sm * G3];   // [b][t][1536]
__device__ float    g_rnn[(size_t)Bm_ * Sm * Dm];  // [b][t][512]
__device__ float    g_h[2][Dm * Bm_];              // ping-pong H, [k][b]
__device__ unsigned g_cnt;                         // scan grid-barrier counter
__device__ unsigned g_step;                        // published scan progress (t+1)
__device__ unsigned g_chunk[NCH * 16];             // gi chunk completion (64B stride)

__global__ void init_state()
{
    int tid = blockIdx.x * blockDim.x + threadIdx.x;
    if (tid == 0) { g_cnt = 0u; g_step = 0u; }
    if (tid < NCH * 16) g_chunk[tid] = 0u;
    if (tid < Dm * Bm_) g_h[0][tid] = 0.f;
}

__device__ __forceinline__ unsigned ld_acq(const unsigned* p)
{
    unsigned v;
    asm volatile("ld.acquire.gpu.u32 %0, [%1];" : "=r"(v) : "l"(p) : "memory");
    return v;
}
__device__ __forceinline__ void st_rel(unsigned* p, unsigned v)
{
    asm volatile("st.release.gpu.u32 [%0], %1;" :: "l"(p), "r"(v) : "memory");
}

// ---------------------------------------------------------------------------
// One 128x64 fp32 GEMM tile: C[m0:+128, n0:+64] = A[m0:+128, :K] @ B[:K, n0:+64] + bias
// ---------------------------------------------------------------------------
__device__ __forceinline__ void gemm_tile(
    const float* __restrict__ A, const float* __restrict__ Bmat,
    const float* __restrict__ bias, float* __restrict__ C,
    int m0, int n0, int N, int K, float* sm)
{
    float* As = sm;              // [16][132]
    float* Bs = sm + 16 * 132;   // [16][64]

    const int tid = threadIdx.x;
    const int tx = tid & 15;
    const int ty = tid >> 4;
    const int a_row = tid >> 2;
    const int a_kq  = (tid & 3) * 4;

    float acc[8][4];
#pragma unroll
    for (int i = 0; i < 8; ++i)
#pragma unroll
        for (int j = 0; j < 4; ++j) acc[i][j] = 0.f;

    for (int k0 = 0; k0 < K; k0 += 16) {
#pragma unroll
        for (int j = 0; j < 2; ++j) {
            int row = a_row + j * 64;
            float4 v = *(const float4*)(A + (size_t)(m0 + row) * K + k0 + a_kq);
            As[(a_kq + 0) * 132 + row] = v.x;
            As[(a_kq + 1) * 132 + row] = v.y;
            As[(a_kq + 2) * 132 + row] = v.z;
            As[(a_kq + 3) * 132 + row] = v.w;
        }
        {
            float4 v = *(const float4*)(Bmat + (size_t)(k0 + ty) * N + n0 + tx * 4);
            *(float4*)&Bs[ty * 64 + tx * 4] = v;
        }
        __syncthreads();
#pragma unroll
        for (int kk = 0; kk < 16; ++kk) {
            float a[8], b[4];
            *(float4*)&a[0] = *(const float4*)&As[kk * 132 + ty * 8];
            *(float4*)&a[4] = *(const float4*)&As[kk * 132 + ty * 8 + 4];
            *(float4*)&b[0] = *(const float4*)&Bs[kk * 64 + tx * 4];
#pragma unroll
            for (int i = 0; i < 8; ++i)
#pragma unroll
                for (int j = 0; j < 4; ++j)
                    acc[i][j] += a[i] * b[j];
        }
        __syncthreads();
    }

    float4 bv = *(const float4*)(bias + n0 + tx * 4);
#pragma unroll
    for (int i = 0; i < 8; ++i) {
        float4 o;
        o.x = acc[i][0] + bv.x;
        o.y = acc[i][1] + bv.y;
        o.z = acc[i][2] + bv.z;
        o.w = acc[i][3] + bv.w;
        *(float4*)(C + (size_t)(m0 + ty * 8 + i) * N + n0 + tx * 4) = o;
    }
}

// ---------------------------------------------------------------------------
// Scan role: block owns 4 h-dims (12 Wh cols resident in SMEM all 4096 steps)
// ---------------------------------------------------------------------------
__device__ void scan_role(int bid, const float* __restrict__ Wh,
                          const float* __restrict__ bhn, float* sm)
{
    float* wh_s = sm;                  // [512][12]
    float* h_s  = sm + Dm * 12;        // [512][16]
    float* red  = sm + Dm * 12 + Dm * 16;  // [12][8][16]

    const int tid = threadIdx.x;
    const int d0  = bid * 4;

    for (int i = tid; i < Dm * 3; i += 256) {
        int k = i / 3, g = i - k * 3;
        float4 v = *(const float4*)(Wh + (size_t)k * G3 + g * Dm + d0);
        *(float4*)&wh_s[k * 12 + g * 4] = v;
    }

    const int warp = tid >> 5, lane = tid & 31;
    const int b  = lane & 15;
    const int kg = lane >> 4;
    const int gd = tid >> 4, gb = tid & 15;
    float my_bhn = 0.f;
    if (tid < 64) my_bhn = bhn[d0 + gd];

    const float4* whv = (const float4*)wh_s;
    unsigned target = 0;

    for (int t = 0; t < Sm; ++t) {
        // gate on gi producer chunk (once per 128 steps)
        if ((t & (TCH - 1)) == 0) {
            if (tid == 0) {
                const unsigned* cc = &g_chunk[(t >> 7) * 16];
                while (ld_acq(cc) < (unsigned)T1PC) { }
            }
            __syncthreads();
        }

        const float* Hc = g_h[t & 1];
        float* Hn = g_h[(t & 1) ^ 1];

        float gir = 0.f, giz = 0.f, gin = 0.f;
        if (tid < 64) {
            const float* gp = g_gi + ((size_t)gb * Sm + t) * G3 + d0 + gd;
            gir = gp[0]; giz = gp[Dm]; gin = gp[2 * Dm];
        }

#pragma unroll
        for (int i = 0; i < 8; ++i) {
            int idx = (tid + i * 256) << 2;
            *(float4*)&h_s[idx] = *(const float4*)&Hc[idx];
        }
        __syncthreads();

        // 12 columns x 1 batch per lane, 32 interleaved k per lane
        float acc[12];
#pragma unroll
        for (int j = 0; j < 12; ++j) acc[j] = 0.f;
#pragma unroll 4
        for (int i = 0; i < 32; ++i) {
            int k = (warp << 6) + (i << 1) + kg;
            float hv = h_s[(k << 4) + b];
            float4 w0 = whv[k * 3 + 0];
            float4 w1 = whv[k * 3 + 1];
            float4 w2 = whv[k * 3 + 2];
            acc[0] += w0.x * hv; acc[1] += w0.y * hv; acc[2]  += w0.z * hv; acc[3]  += w0.w * hv;
            acc[4] += w1.x * hv; acc[5] += w1.y * hv; acc[6]  += w1.z * hv; acc[7]  += w1.w * hv;
            acc[8] += w2.x * hv; acc[9] += w2.y * hv; acc[10] += w2.z * hv; acc[11] += w2.w * hv;
        }
#pragma unroll
        for (int j = 0; j < 12; ++j)
            acc[j] += __shfl_xor_sync(0xffffffffu, acc[j], 16);
        if (kg == 0) {
#pragma unroll
            for (int j = 0; j < 12; ++j)
                red[j * 128 + warp * 16 + b] = acc[j];
        }
        __syncthreads();

        if (tid < 64) {
            float ghr = 0.f, ghz = 0.f, ghn = 0.f;
#pragma unroll
            for (int w = 0; w < 8; ++w) {
                ghr += red[(0 + gd) * 128 + w * 16 + gb];
                ghz += red[(4 + gd) * 128 + w * 16 + gb];
                ghn += red[(8 + gd) * 128 + w * 16 + gb];
            }
            float r = 1.f / (1.f + __expf(-(gir + ghr)));
            float z = 1.f / (1.f + __expf(-(giz + ghz)));
            float n = tanhf(gin + r * (ghn + my_bhn));
            float hold = h_s[((d0 + gd) << 4) + gb];
            float hnew = (1.f - z) * n + z * hold;
            Hn[((d0 + gd) << 4) + gb] = hnew;
            g_rnn[((size_t)gb * Sm + t) * Dm + d0 + gd] = hnew;
        }
        __syncthreads();

        // grid barrier across the 128 scan blocks (monotone counter)
        target += NSCAN;
        if (tid == 0) {
            __threadfence();
            atomicAdd(&g_cnt, 1u);
            while (ld_acq(&g_cnt) < target) { }
            if (bid == 0) st_rel(&g_step, (unsigned)(t + 1));
        }
        __syncthreads();
    }
}

// ---------------------------------------------------------------------------
// Fused heterogeneous-grid kernel
// ---------------------------------------------------------------------------
extern __shared__ float smem_dyn[];

__global__ void __launch_bounds__(256, 3) fused_kernel(
    const float* __restrict__ x,  const float* __restrict__ Wi,
    const float* __restrict__ bi, const float* __restrict__ Wh,
    const float* __restrict__ bhn, const float* __restrict__ Wo,
    const float* __restrict__ bo, float* __restrict__ out)
{
    const int bid = blockIdx.x;
    float* sm = smem_dyn;

    if (bid < NSCAN) {
        scan_role(bid, Wh, bhn, sm);
    } else if (bid < NSCAN + NT1) {
        // gi producer tile: ordered (chunk, batch, ncol)
        int tt = bid - NSCAN;
        int tc = tt / T1PC;
        int r  = tt - tc * T1PC;
        int bb = r / 24;
        int nn = r - bb * 24;
        int m0 = bb * Sm + tc * TCH;
        gemm_tile(x, Wi, bi, g_gi, m0, nn * 64, G3, Dm, sm);
        __syncthreads();
        if (threadIdx.x == 0) {
            __threadfence();
            atomicAdd(&g_chunk[tc * 16], 1u);
        }
    } else {
        // output consumer tile: waits until scan passed its t-range
        int tt = bid - NSCAN - NT1;
        int tc = tt / T2PC;
        int r  = tt - tc * T2PC;
        int bb = r / 8;
        int nn = r - bb * 8;
        unsigned need = (unsigned)((tc + 1) * TCH);
        if (threadIdx.x == 0) {
            while (ld_acq(&g_step) < need) __nanosleep(200);
        }
        __syncthreads();
        int m0 = bb * Sm + tc * TCH;
        gemm_tile(g_rnn, Wo, bo, out, m0, nn * 64, Dm, Dm, sm);
    }
}

// ---------------------------------------------------------------------------
extern "C" void kernel_launch(void* const* d_in, const int* in_sizes, int n_in,
                              void* d_out, int out_size)
{
    const float* x   = (const float*)d_in[0];
    const float* Wi  = (const float*)d_in[1];
    const float* bi  = (const float*)d_in[2];
    const float* Wh  = (const float*)d_in[3];
    const float* bhn = (const float*)d_in[4];
    const float* Wo  = (const float*)d_in[5];
    const float* bo  = (const float*)d_in[6];
    float* out = (float*)d_out;

    cudaFuncSetAttribute(fused_kernel,
                         cudaFuncAttributeMaxDynamicSharedMemorySize, SMEMB);

    init_state<<<32, 256>>>();
    fused_kernel<<<NTOT, 256, SMEMB>>>(x, Wi, bi, Wh, bhn, Wo, bo, out);
}

// round 5
// speedup vs baseline: 1.2049x; 1.2049x over previous
#include <cuda_runtime.h>
#include <cstdint>
#include <cstddef>

#define Dm   512
#define Bm_  16
#define Sm   4096
#define G3   1536
#define NBLK 128
#define NTHR 256

// Scratch (device globals: allocation-free per harness rules)
__device__ float    g_gi[(size_t)Bm_ * Sm * G3];   // [b][t][1536]
__device__ float    g_rnn[(size_t)Bm_ * Sm * Dm];  // [b][t][512]
__device__ float    g_h[2][Dm * Bm_];              // ping-pong H, [k][b] layout
__device__ unsigned g_cnt;                         // grid barrier counter

__global__ void init_state()
{
    int tid = blockIdx.x * blockDim.x + threadIdx.x;
    if (tid == 0) g_cnt = 0u;
    if (tid < Dm * Bm_) g_h[0][tid] = 0.f;
}

__device__ __forceinline__ unsigned ld_acq(const unsigned* p)
{
    unsigned v;
    asm volatile("ld.acquire.gpu.u32 %0, [%1];" : "=r"(v) : "l"(p) : "memory");
    return v;
}

// packed fp32x2 fma: d = a*b + d  (componentwise on 2 floats)
__device__ __forceinline__ void ffma2(unsigned long long& d,
                                      unsigned long long a,
                                      unsigned long long b)
{
    asm("fma.rn.f32x2 %0, %1, %2, %0;" : "+l"(d) : "l"(a), "l"(b));
}

__device__ __forceinline__ void ld_s_v2u64(unsigned long long& a,
                                           unsigned long long& b,
                                           unsigned saddr)
{
    asm("ld.shared.v2.u64 {%0,%1}, [%2];" : "=l"(a), "=l"(b) : "r"(saddr));
}

// ---------------------------------------------------------------------------
// SGEMM: C[M,N] = A[M,K] @ B[K,N] + bias[N]   (BM=128, BN=64, BK=16)
// ---------------------------------------------------------------------------
__global__ void __launch_bounds__(256) sgemm_bias(
    const float* __restrict__ A, const float* __restrict__ Bmat,
    const float* __restrict__ bias, float* __restrict__ C,
    int M, int N, int K)
{
    __shared__ float As[16][132];
    __shared__ float Bs[16][64];

    const int tid = threadIdx.x;
    const int tx = tid & 15;
    const int ty = tid >> 4;
    const int m0 = blockIdx.y * 128;
    const int n0 = blockIdx.x * 64;

    const int a_row = tid >> 2;
    const int a_kq  = (tid & 3) * 4;

    float acc[8][4];
#pragma unroll
    for (int i = 0; i < 8; ++i)
#pragma unroll
        for (int j = 0; j < 4; ++j) acc[i][j] = 0.f;

    for (int k0 = 0; k0 < K; k0 += 16) {
#pragma unroll
        for (int j = 0; j < 2; ++j) {
            int row = a_row + j * 64;
            float4 v = *(const float4*)(A + (size_t)(m0 + row) * K + k0 + a_kq);
            As[a_kq + 0][row] = v.x;
            As[a_kq + 1][row] = v.y;
            As[a_kq + 2][row] = v.z;
            As[a_kq + 3][row] = v.w;
        }
        {
            float4 v = *(const float4*)(Bmat + (size_t)(k0 + ty) * N + n0 + tx * 4);
            *(float4*)&Bs[ty][tx * 4] = v;
        }
        __syncthreads();
#pragma unroll
        for (int kk = 0; kk < 16; ++kk) {
            float a[8], b[4];
            *(float4*)&a[0] = *(const float4*)&As[kk][ty * 8];
            *(float4*)&a[4] = *(const float4*)&As[kk][ty * 8 + 4];
            *(float4*)&b[0] = *(const float4*)&Bs[kk][tx * 4];
#pragma unroll
            for (int i = 0; i < 8; ++i)
#pragma unroll
                for (int j = 0; j < 4; ++j)
                    acc[i][j] += a[i] * b[j];
        }
        __syncthreads();
    }

    float4 bv = *(const float4*)(bias + n0 + tx * 4);
#pragma unroll
    for (int i = 0; i < 8; ++i) {
        float4 o;
        o.x = acc[i][0] + bv.x;
        o.y = acc[i][1] + bv.y;
        o.z = acc[i][2] + bv.z;
        o.w = acc[i][3] + bv.w;
        *(float4*)(C + (size_t)(m0 + ty * 8 + i) * N + n0 + tx * 4) = o;
    }
}

// ---------------------------------------------------------------------------
// Persistent GRU scan, FFMA2 (fp32x2) inner loop.
// 128 blocks x 256 threads; block owns 4 h-dims (12 Wh columns, stored
// duplicated (w,w) in SMEM for packed math). Lane = batch-pair(8) x kg(4).
// ---------------------------------------------------------------------------
extern __shared__ float smem_dyn[];

__global__ void __launch_bounds__(NTHR, 1) gru_scan(
    const float* __restrict__ Wh, const float* __restrict__ bhn)
{
    float* wh2 = smem_dyn;                       // [512][24]  dup weights
    float* h_s = smem_dyn + Dm * 24;             // [512][16]
    float* red = smem_dyn + Dm * 24 + Dm * 16;   // [12][128]

    const int tid = threadIdx.x;
    const int d0  = blockIdx.x * 4;

    // one-time: load + duplicate Wh column slice
    for (int i = tid; i < Dm * 12; i += NTHR) {
        int k = i / 12, j = i - k * 12;
        int g = j >> 2, jd = j & 3;
        float w = Wh[(size_t)k * G3 + g * Dm + d0 + jd];
        wh2[k * 24 + j * 2 + 0] = w;
        wh2[k * 24 + j * 2 + 1] = w;
    }

    const int warp = tid >> 5, lane = tid & 31;
    const int bp = lane & 7;           // batch pair -> batches 2bp, 2bp+1
    const int kg = lane >> 3;          // 0..3
    const int gd = tid >> 4, gb = tid & 15;   // gate mapping (tid<64)
    float my_bhn = 0.f;
    if (tid < 64) my_bhn = bhn[d0 + gd];

    const unsigned wh2_base = (unsigned)__cvta_generic_to_shared(wh2);
    unsigned target = 0;

    for (int t = 0; t < Sm; ++t) {
        const float* Hc = g_h[t & 1];
        float* Hn = g_h[(t & 1) ^ 1];

        // prefetch input-side gates (DRAM latency covered by k-loop)
        float gir = 0.f, giz = 0.f, gin = 0.f;
        if (tid < 64) {
            const float* gp = g_gi + ((size_t)gb * Sm + t) * G3 + d0 + gd;
            gir = __ldg(gp); giz = __ldg(gp + Dm); gin = __ldg(gp + 2 * Dm);
        }

        // load H state (coalesced)
#pragma unroll
        for (int i = 0; i < 8; ++i) {
            int idx = (tid + i * NTHR) << 2;
            *(float4*)&h_s[idx] = *(const float4*)&Hc[idx];
        }
        __syncthreads();

        // packed k-loop: 16 k per lane, 12 col-accumulators x 2 batches
        unsigned long long acc[12];
#pragma unroll
        for (int j = 0; j < 12; ++j) acc[j] = 0ull;

#pragma unroll 4
        for (int i = 0; i < 16; ++i) {
            int k = (warp << 6) + (i << 2) + kg;
            unsigned long long hv =
                *(const unsigned long long*)&h_s[(k << 4) + (bp << 1)];
            unsigned saddr = wh2_base + (unsigned)(k * 96);
            unsigned long long w0, w1, w2, w3, w4, w5;
            ld_s_v2u64(w0, w1, saddr);
            ld_s_v2u64(w2, w3, saddr + 16);
            ld_s_v2u64(w4, w5, saddr + 32);
            ffma2(acc[0],  w0, hv);
            ffma2(acc[1],  w1, hv);
            ffma2(acc[2],  w2, hv);
            ffma2(acc[3],  w3, hv);
            ffma2(acc[4],  w4, hv);
            ffma2(acc[5],  w5, hv);
            ld_s_v2u64(w0, w1, saddr + 48);
            ld_s_v2u64(w2, w3, saddr + 64);
            ld_s_v2u64(w4, w5, saddr + 80);
            ffma2(acc[6],  w0, hv);
            ffma2(acc[7],  w1, hv);
            ffma2(acc[8],  w2, hv);
            ffma2(acc[9],  w3, hv);
            ffma2(acc[10], w4, hv);
            ffma2(acc[11], w5, hv);
        }

        // reduce over kg (lane bits 3,4), then kg==0 lanes write partials
        float aL[12], aH[12];
#pragma unroll
        for (int j = 0; j < 12; ++j) {
            asm("mov.b64 {%0,%1}, %2;" : "=f"(aL[j]), "=f"(aH[j]) : "l"(acc[j]));
            aL[j] += __shfl_xor_sync(0xffffffffu, aL[j], 8);
            aH[j] += __shfl_xor_sync(0xffffffffu, aH[j], 8);
            aL[j] += __shfl_xor_sync(0xffffffffu, aL[j], 16);
            aH[j] += __shfl_xor_sync(0xffffffffu, aH[j], 16);
        }
        if (kg == 0) {
#pragma unroll
            for (int j = 0; j < 12; ++j) {
                float2 v = make_float2(aL[j], aH[j]);
                *(float2*)&red[j * 128 + warp * 16 + (bp << 1)] = v;
            }
        }
        __syncthreads();

        if (tid < 64) {
            float ghr = 0.f, ghz = 0.f, ghn = 0.f;
#pragma unroll
            for (int w = 0; w < 8; ++w) {
                ghr += red[(0 + gd) * 128 + w * 16 + gb];
                ghz += red[(4 + gd) * 128 + w * 16 + gb];
                ghn += red[(8 + gd) * 128 + w * 16 + gb];
            }
            float r = 1.f / (1.f + __expf(-(gir + ghr)));
            float z = 1.f / (1.f + __expf(-(giz + ghz)));
            float n = tanhf(gin + r * (ghn + my_bhn));
            float hold = h_s[((d0 + gd) << 4) + gb];
            float hnew = (1.f - z) * n + z * hold;
            Hn[((d0 + gd) << 4) + gb] = hnew;
            g_rnn[((size_t)gb * Sm + t) * Dm + d0 + gd] = hnew;
        }
        __syncthreads();

        // grid barrier across 128 scan blocks (monotone counter)
        target += NBLK;
        if (tid == 0) {
            __threadfence();
            atomicAdd(&g_cnt, 1u);
            while (ld_acq(&g_cnt) < target) { }
        }
        __syncthreads();
    }
}

// ---------------------------------------------------------------------------
extern "C" void kernel_launch(void* const* d_in, const int* in_sizes, int n_in,
                              void* d_out, int out_size)
{
    const float* x   = (const float*)d_in[0];
    const float* Wi  = (const float*)d_in[1];
    const float* bi  = (const float*)d_in[2];
    const float* Wh  = (const float*)d_in[3];
    const float* bhn = (const float*)d_in[4];
    const float* Wo  = (const float*)d_in[5];
    const float* bo  = (const float*)d_in[6];
    float* out = (float*)d_out;

    void* gi_ptr = nullptr;
    void* rnn_ptr = nullptr;
    cudaGetSymbolAddress(&gi_ptr, g_gi);
    cudaGetSymbolAddress(&rnn_ptr, g_rnn);

    const int smem_bytes = (Dm * 24 + Dm * 16 + 12 * 128) * (int)sizeof(float); // 88064
    cudaFuncSetAttribute(gru_scan, cudaFuncAttributeMaxDynamicSharedMemorySize, smem_bytes);

    init_state<<<32, 256>>>();

    dim3 g1(G3 / 64, (Bm_ * Sm) / 128);
    sgemm_bias<<<g1, 256>>>(x, Wi, bi, (float*)gi_ptr, Bm_ * Sm, G3, Dm);

    gru_scan<<<NBLK, NTHR, smem_bytes>>>(Wh, bhn);

    dim3 g2(Dm / 64, (Bm_ * Sm) / 128);
    sgemm_bias<<<g2, 256>>>((const float*)rnn_ptr, Wo, bo, out, Bm_ * Sm, Dm, Dm);
}